// round 9
// baseline (speedup 1.0000x reference)
#include <cuda_runtime.h>
#include <cuda_fp16.h>
#include <cuda_bf16.h>

// LightGCN on GB300 — v9: software-pipelined SpMM gathers.
// v8 + ONE hot-loop change: each quarter-warp group batches 4 edge loads,
// then issues 4 independent row gathers, then the FMA block (16 outstanding
// gathers per warp instead of 8 — attacks exposed L2 latency).

#define N_USERS 100000
#define M_ITEMS 50000
#define NN      (N_USERS + M_ITEMS)   // 150000
#define DVEC    16                    // D=64 floats = 16 float4
#define QVEC    8                     // D=64 halfs  = 8 uint4
#define ELEMN   (NN * DVEC)           // 2.4M float4
#define INV_SCALE (1.0f / 16.0f)      // 1/(LAYERS+1)^2
#define CAP     128                   // ELL row capacity (Poisson(26.7) safe)
#define CAPSH   7

// Static device scratch (allocation-free). Zero-initialized at module load.
__device__ uint4  g_h[3][NN * QVEC];      // fp16: h0=input, h1=e1, h2=e2
__device__ float4 g_e3[ELEMN];            // fp32 e3 (pure store)
__device__ int    g_len[NN];              // ELL row lengths (zeroed by dot)
__device__ int2   g_edge[NN * CAP];       // padded ELL (col, val)

__device__ __forceinline__ unsigned pack_h2(float x, float y) {
    __half2 p = __floats2half2_rn(x, y);
    return *reinterpret_cast<unsigned*>(&p);
}

// ---------------------------------------------------------------------------
// setup: fp16 table init + single-pass ELL edge scatter (fused)
// ---------------------------------------------------------------------------
__global__ void lgcn_setup(const float* __restrict__ user_emb,
                           const float* __restrict__ item_emb,
                           const int*   __restrict__ rows,
                           const int*   __restrict__ cols,
                           const float* __restrict__ vals, int E) {
    int i = blockIdx.x * blockDim.x + threadIdx.x;
    if (i < ELEMN) {
        float4 v;
        if (i < N_USERS * DVEC) {
            v = reinterpret_cast<const float4*>(user_emb)[i];
        } else {
            v = reinterpret_cast<const float4*>(item_emb)[i - N_USERS * DVEC];
        }
        uint2* h2 = reinterpret_cast<uint2*>(g_h[0]);
        uint2 u;
        u.x = pack_h2(v.x, v.y);
        u.y = pack_h2(v.z, v.w);
        h2[i] = u;
    }
    for (int e = i; e < E; e += ELEMN) {
        int r   = __ldg(&rows[e]);
        int pos = atomicAdd(&g_len[r], 1);
        g_edge[(r << CAPSH) + pos] =
            make_int2(__ldg(&cols[e]), __float_as_int(__ldg(&vals[e])));
    }
}

// ---------------------------------------------------------------------------
// ELL SpMM: one warp per row, 4 quarter-warp edge groups; each lane loads one
// uint4 (8 halves, 16B), 8 lanes cover the 128B fp16 row. fp32 accumulation.
// Main loop: 4 edges per group-iteration, loads batched for MLP.
// ---------------------------------------------------------------------------
__device__ __forceinline__ void fma8(float* a, float v, uint4 h) {
    float2 f0 = __half22float2(*reinterpret_cast<__half2*>(&h.x));
    float2 f1 = __half22float2(*reinterpret_cast<__half2*>(&h.y));
    float2 f2 = __half22float2(*reinterpret_cast<__half2*>(&h.z));
    float2 f3 = __half22float2(*reinterpret_cast<__half2*>(&h.w));
    a[0] += v * f0.x; a[1] += v * f0.y;
    a[2] += v * f1.x; a[3] += v * f1.y;
    a[4] += v * f2.x; a[5] += v * f2.y;
    a[6] += v * f3.x; a[7] += v * f3.y;
}

__global__ void lgcn_spmm_ell(int src, int dst, int fp16Out) {
    int w = (blockIdx.x * blockDim.x + threadIdx.x) >> 5;   // row
    if (w >= NN) return;
    int lane = threadIdx.x & 31;
    int grp  = lane >> 3;     // 0..3
    int comp = lane & 7;      // uint4 index within row

    int start = w << CAPSH;
    int end   = start + __ldg(&g_len[w]);

    const uint4* __restrict__ S = g_h[src];
    float a[8] = {0.f, 0.f, 0.f, 0.f, 0.f, 0.f, 0.f, 0.f};

    int e = start + grp;
    // pipelined main loop: 4 edges per group per iteration
    for (; e + 12 < end; e += 16) {
        int2 cv0 = __ldg(&g_edge[e]);
        int2 cv1 = __ldg(&g_edge[e + 4]);
        int2 cv2 = __ldg(&g_edge[e + 8]);
        int2 cv3 = __ldg(&g_edge[e + 12]);
        uint4 h0 = __ldg(&S[cv0.x * QVEC + comp]);
        uint4 h1 = __ldg(&S[cv1.x * QVEC + comp]);
        uint4 h2 = __ldg(&S[cv2.x * QVEC + comp]);
        uint4 h3 = __ldg(&S[cv3.x * QVEC + comp]);
        fma8(a, __int_as_float(cv0.y), h0);
        fma8(a, __int_as_float(cv1.y), h1);
        fma8(a, __int_as_float(cv2.y), h2);
        fma8(a, __int_as_float(cv3.y), h3);
    }
    // remainder
    for (; e < end; e += 4) {
        int2  cv = __ldg(&g_edge[e]);
        uint4 h  = __ldg(&S[cv.x * QVEC + comp]);
        fma8(a, __int_as_float(cv.y), h);
    }

    #pragma unroll
    for (int off = 8; off <= 16; off <<= 1) {
        #pragma unroll
        for (int k = 0; k < 8; k++)
            a[k] += __shfl_xor_sync(0xFFFFFFFFu, a[k], off);
    }

    if (grp == 0) {
        if (fp16Out) {
            uint4 hout;
            hout.x = pack_h2(a[0], a[1]);
            hout.y = pack_h2(a[2], a[3]);
            hout.z = pack_h2(a[4], a[5]);
            hout.w = pack_h2(a[6], a[7]);
            g_h[dst][(w << 3) + comp] = hout;
        } else {
            int o = w * DVEC + comp * 2;
            g_e3[o]     = make_float4(a[0], a[1], a[2], a[3]);
            g_e3[o + 1] = make_float4(a[4], a[5], a[6], a[7]);
        }
    }
}

// ---------------------------------------------------------------------------
// dot: one warp per (user, item) pair.
// acc[node] = input_fp32[node] + h1[node] + h2[node] + e3[node], on the fly.
// Tail zeroes g_len for the next call.
// ---------------------------------------------------------------------------
__global__ void lgcn_dot(const int* __restrict__ users,
                         const int* __restrict__ items,
                         const float* __restrict__ uemb,
                         const float* __restrict__ iemb,
                         float* __restrict__ out, int B) {
    int gt   = blockIdx.x * blockDim.x + threadIdx.x;
    int w    = gt >> 5;
    int lane = gt & 31;

    if (w < B) {
        int u  = __ldg(&users[w]);
        int it = __ldg(&items[w]);
        int ni = N_USERS + it;

        const unsigned* H1 = reinterpret_cast<const unsigned*>(g_h[1]);
        const unsigned* H2 = reinterpret_cast<const unsigned*>(g_h[2]);
        const float2*   E3 = reinterpret_cast<const float2*>(g_e3);

        float2 su = __ldg(reinterpret_cast<const float2*>(uemb) + u * 32 + lane);
        {
            float2 t;
            t = __half22float2(*reinterpret_cast<const __half2*>(&H1[u * 32 + lane]));
            su.x += t.x; su.y += t.y;
            t = __half22float2(*reinterpret_cast<const __half2*>(&H2[u * 32 + lane]));
            su.x += t.x; su.y += t.y;
            float2 e = E3[u * 32 + lane];
            su.x += e.x; su.y += e.y;
        }
        float2 si = __ldg(reinterpret_cast<const float2*>(iemb) + it * 32 + lane);
        {
            float2 t;
            t = __half22float2(*reinterpret_cast<const __half2*>(&H1[ni * 32 + lane]));
            si.x += t.x; si.y += t.y;
            t = __half22float2(*reinterpret_cast<const __half2*>(&H2[ni * 32 + lane]));
            si.x += t.x; si.y += t.y;
            float2 e = E3[ni * 32 + lane];
            si.x += e.x; si.y += e.y;
        }

        float s = su.x * si.x + su.y * si.y;
        #pragma unroll
        for (int off = 16; off > 0; off >>= 1)
            s += __shfl_xor_sync(0xFFFFFFFFu, s, off);

        if (lane == 0) out[w] = s * INV_SCALE;
    }

    // precondition for next call: g_len = 0
    int nt = gridDim.x * blockDim.x;
    for (int i = gt; i < NN; i += nt) g_len[i] = 0;
}

// ---------------------------------------------------------------------------
// kernel_launch
// Inputs: 0 users(i32,B) 1 items(i32,B) 2 user_emb(f32) 3 item_emb(f32)
//         4 adj_rows(i32,NNZ) 5 adj_cols(i32,NNZ) 6 adj_vals(f32,NNZ)
// ---------------------------------------------------------------------------
extern "C" void kernel_launch(void* const* d_in, const int* in_sizes, int n_in,
                              void* d_out, int out_size) {
    const int*   users    = (const int*)  d_in[0];
    const int*   items    = (const int*)  d_in[1];
    const float* user_emb = (const float*)d_in[2];
    const float* item_emb = (const float*)d_in[3];
    const int*   rows     = (const int*)  d_in[4];
    const int*   cols     = (const int*)  d_in[5];
    const float* vals     = (const float*)d_in[6];
    float*       out      = (float*)      d_out;

    const int E = in_sizes[4];
    const int B = in_sizes[0];

    const int TPB    = 256;
    const int gSetup = (ELEMN + TPB - 1) / TPB;
    const int gSpmm  = (NN * 32 + TPB - 1) / TPB;
    const int gDot   = (B * 32 + TPB - 1) / TPB;

    lgcn_setup<<<gSetup, TPB>>>(user_emb, item_emb, rows, cols, vals, E);

    lgcn_spmm_ell<<<gSpmm, TPB>>>(0, 1, 1);   // e1 -> h1 (fp16)
    lgcn_spmm_ell<<<gSpmm, TPB>>>(1, 2, 1);   // e2 -> h2 (fp16)
    lgcn_spmm_ell<<<gSpmm, TPB>>>(2, 0, 0);   // e3 -> g_e3 (fp32)

    lgcn_dot<<<gDot, TPB>>>(users, items, user_emb, item_emb, out, B);
}

// round 10
// speedup vs baseline: 1.0254x; 1.0254x over previous
#include <cuda_runtime.h>
#include <cuda_fp16.h>
#include <cuda_bf16.h>

// LightGCN on GB300 — v10: v8 structure + packed f32x2 FMA in the SpMM loop.
//  - three fp16 layer buffers h0/h1/h2; layer-3 pure-stores fp32 e3
//  - dot reconstructs acc = input + e1 + e2 + e3 for sampled nodes
//  - ELL single-pass edge build; quarter-warp SpMM groups, unroll 2
//  - NEW: fma.rn.f32x2 accumulation (4 FFMA2 instead of 8 FFMA per edge-lane)

#define N_USERS 100000
#define M_ITEMS 50000
#define NN      (N_USERS + M_ITEMS)   // 150000
#define DVEC    16                    // D=64 floats = 16 float4
#define QVEC    8                     // D=64 halfs  = 8 uint4
#define ELEMN   (NN * DVEC)           // 2.4M float4
#define INV_SCALE (1.0f / 16.0f)      // 1/(LAYERS+1)^2
#define CAP     128                   // ELL row capacity (Poisson(26.7) safe)
#define CAPSH   7

// Static device scratch (allocation-free). Zero-initialized at module load.
__device__ uint4  g_h[3][NN * QVEC];      // fp16: h0=input, h1=e1, h2=e2
__device__ float4 g_e3[ELEMN];            // fp32 e3 (pure store)
__device__ int    g_len[NN];              // ELL row lengths (zeroed by dot)
__device__ int2   g_edge[NN * CAP];       // padded ELL (col, val)

__device__ __forceinline__ unsigned pack_h2(float x, float y) {
    __half2 p = __floats2half2_rn(x, y);
    return *reinterpret_cast<unsigned*>(&p);
}

// packed fp32x2 helpers (Blackwell): pack/unpack are register-pairing only
__device__ __forceinline__ unsigned long long pk2(float lo, float hi) {
    unsigned long long r;
    asm("mov.b64 %0, {%1, %2};" : "=l"(r) : "f"(lo), "f"(hi));
    return r;
}
__device__ __forceinline__ void upk2(float& lo, float& hi, unsigned long long v) {
    asm("mov.b64 {%0, %1}, %2;" : "=f"(lo), "=f"(hi) : "l"(v));
}
__device__ __forceinline__ void ffma2(unsigned long long& acc,
                                      unsigned long long a,
                                      unsigned long long b) {
    asm("fma.rn.f32x2 %0, %1, %2, %0;" : "+l"(acc) : "l"(a), "l"(b));
}

// ---------------------------------------------------------------------------
// setup: fp16 table init + single-pass ELL edge scatter (fused)
// ---------------------------------------------------------------------------
__global__ void lgcn_setup(const float* __restrict__ user_emb,
                           const float* __restrict__ item_emb,
                           const int*   __restrict__ rows,
                           const int*   __restrict__ cols,
                           const float* __restrict__ vals, int E) {
    int i = blockIdx.x * blockDim.x + threadIdx.x;
    if (i < ELEMN) {
        float4 v;
        if (i < N_USERS * DVEC) {
            v = reinterpret_cast<const float4*>(user_emb)[i];
        } else {
            v = reinterpret_cast<const float4*>(item_emb)[i - N_USERS * DVEC];
        }
        uint2* h2 = reinterpret_cast<uint2*>(g_h[0]);
        uint2 u;
        u.x = pack_h2(v.x, v.y);
        u.y = pack_h2(v.z, v.w);
        h2[i] = u;
    }
    for (int e = i; e < E; e += ELEMN) {
        int r   = __ldg(&rows[e]);
        int pos = atomicAdd(&g_len[r], 1);
        g_edge[(r << CAPSH) + pos] =
            make_int2(__ldg(&cols[e]), __float_as_int(__ldg(&vals[e])));
    }
}

// ---------------------------------------------------------------------------
// ELL SpMM: one warp per row, 4 quarter-warp edge groups; each lane loads one
// uint4 (8 halves, 16B), 8 lanes cover the 128B fp16 row.
// fp32 accumulation in 4 packed f32x2 registers (fma.rn.f32x2).
// ---------------------------------------------------------------------------
__device__ __forceinline__ void fma8p(unsigned long long* acc,
                                      unsigned long long vv, uint4 h) {
    float2 f0 = __half22float2(*reinterpret_cast<__half2*>(&h.x));
    float2 f1 = __half22float2(*reinterpret_cast<__half2*>(&h.y));
    float2 f2 = __half22float2(*reinterpret_cast<__half2*>(&h.z));
    float2 f3 = __half22float2(*reinterpret_cast<__half2*>(&h.w));
    ffma2(acc[0], vv, pk2(f0.x, f0.y));
    ffma2(acc[1], vv, pk2(f1.x, f1.y));
    ffma2(acc[2], vv, pk2(f2.x, f2.y));
    ffma2(acc[3], vv, pk2(f3.x, f3.y));
}

__global__ void lgcn_spmm_ell(int src, int dst, int fp16Out) {
    int w = (blockIdx.x * blockDim.x + threadIdx.x) >> 5;   // row
    if (w >= NN) return;
    int lane = threadIdx.x & 31;
    int grp  = lane >> 3;     // 0..3
    int comp = lane & 7;      // uint4 index within row

    int start = w << CAPSH;
    int end   = start + __ldg(&g_len[w]);

    const uint4* __restrict__ S = g_h[src];
    unsigned long long acc[4];
    acc[0] = acc[1] = acc[2] = acc[3] = pk2(0.f, 0.f);

    #pragma unroll 2
    for (int e = start + grp; e < end; e += 4) {
        int2  cv = __ldg(&g_edge[e]);
        float v  = __int_as_float(cv.y);
        uint4 h  = __ldg(&S[(cv.x << 3) + comp]);
        fma8p(acc, pk2(v, v), h);
    }

    float a[8];
    upk2(a[0], a[1], acc[0]);
    upk2(a[2], a[3], acc[1]);
    upk2(a[4], a[5], acc[2]);
    upk2(a[6], a[7], acc[3]);

    #pragma unroll
    for (int off = 8; off <= 16; off <<= 1) {
        #pragma unroll
        for (int k = 0; k < 8; k++)
            a[k] += __shfl_xor_sync(0xFFFFFFFFu, a[k], off);
    }

    if (grp == 0) {
        if (fp16Out) {
            uint4 hout;
            hout.x = pack_h2(a[0], a[1]);
            hout.y = pack_h2(a[2], a[3]);
            hout.z = pack_h2(a[4], a[5]);
            hout.w = pack_h2(a[6], a[7]);
            g_h[dst][(w << 3) + comp] = hout;
        } else {
            int o = w * DVEC + comp * 2;
            g_e3[o]     = make_float4(a[0], a[1], a[2], a[3]);
            g_e3[o + 1] = make_float4(a[4], a[5], a[6], a[7]);
        }
    }
}

// ---------------------------------------------------------------------------
// dot: one warp per (user, item) pair.
// acc[node] = input_fp32[node] + h1[node] + h2[node] + e3[node], on the fly.
// Tail zeroes g_len for the next call.
// ---------------------------------------------------------------------------
__global__ void lgcn_dot(const int* __restrict__ users,
                         const int* __restrict__ items,
                         const float* __restrict__ uemb,
                         const float* __restrict__ iemb,
                         float* __restrict__ out, int B) {
    int gt   = blockIdx.x * blockDim.x + threadIdx.x;
    int w    = gt >> 5;
    int lane = gt & 31;

    if (w < B) {
        int u  = __ldg(&users[w]);
        int it = __ldg(&items[w]);
        int ni = N_USERS + it;

        const unsigned* H1 = reinterpret_cast<const unsigned*>(g_h[1]);
        const unsigned* H2 = reinterpret_cast<const unsigned*>(g_h[2]);
        const float2*   E3 = reinterpret_cast<const float2*>(g_e3);

        float2 su = __ldg(reinterpret_cast<const float2*>(uemb) + u * 32 + lane);
        {
            float2 t;
            t = __half22float2(*reinterpret_cast<const __half2*>(&H1[u * 32 + lane]));
            su.x += t.x; su.y += t.y;
            t = __half22float2(*reinterpret_cast<const __half2*>(&H2[u * 32 + lane]));
            su.x += t.x; su.y += t.y;
            float2 e = E3[u * 32 + lane];
            su.x += e.x; su.y += e.y;
        }
        float2 si = __ldg(reinterpret_cast<const float2*>(iemb) + it * 32 + lane);
        {
            float2 t;
            t = __half22float2(*reinterpret_cast<const __half2*>(&H1[ni * 32 + lane]));
            si.x += t.x; si.y += t.y;
            t = __half22float2(*reinterpret_cast<const __half2*>(&H2[ni * 32 + lane]));
            si.x += t.x; si.y += t.y;
            float2 e = E3[ni * 32 + lane];
            si.x += e.x; si.y += e.y;
        }

        float s = su.x * si.x + su.y * si.y;
        #pragma unroll
        for (int off = 16; off > 0; off >>= 1)
            s += __shfl_xor_sync(0xFFFFFFFFu, s, off);

        if (lane == 0) out[w] = s * INV_SCALE;
    }

    // precondition for next call: g_len = 0
    int nt = gridDim.x * blockDim.x;
    for (int i = gt; i < NN; i += nt) g_len[i] = 0;
}

// ---------------------------------------------------------------------------
// kernel_launch
// Inputs: 0 users(i32,B) 1 items(i32,B) 2 user_emb(f32) 3 item_emb(f32)
//         4 adj_rows(i32,NNZ) 5 adj_cols(i32,NNZ) 6 adj_vals(f32,NNZ)
// ---------------------------------------------------------------------------
extern "C" void kernel_launch(void* const* d_in, const int* in_sizes, int n_in,
                              void* d_out, int out_size) {
    const int*   users    = (const int*)  d_in[0];
    const int*   items    = (const int*)  d_in[1];
    const float* user_emb = (const float*)d_in[2];
    const float* item_emb = (const float*)d_in[3];
    const int*   rows     = (const int*)  d_in[4];
    const int*   cols     = (const int*)  d_in[5];
    const float* vals     = (const float*)d_in[6];
    float*       out      = (float*)      d_out;

    const int E = in_sizes[4];
    const int B = in_sizes[0];

    const int TPB    = 256;
    const int gSetup = (ELEMN + TPB - 1) / TPB;
    const int gSpmm  = (NN * 32 + TPB - 1) / TPB;
    const int gDot   = (B * 32 + TPB - 1) / TPB;

    lgcn_setup<<<gSetup, TPB>>>(user_emb, item_emb, rows, cols, vals, E);

    lgcn_spmm_ell<<<gSpmm, TPB>>>(0, 1, 1);   // e1 -> h1 (fp16)
    lgcn_spmm_ell<<<gSpmm, TPB>>>(1, 2, 1);   // e2 -> h2 (fp16)
    lgcn_spmm_ell<<<gSpmm, TPB>>>(2, 0, 0);   // e3 -> g_e3 (fp32)

    lgcn_dot<<<gDot, TPB>>>(users, items, user_emb, item_emb, out, B);
}

// round 11
// speedup vs baseline: 1.3280x; 1.2951x over previous
#include <cuda_runtime.h>
#include <cuda_fp16.h>
#include <cuda_bf16.h>

// LightGCN on GB300 — v11: sampled layer-3.
// e3 = A @ h2 is only consumed by the dot at <=8192 sampled nodes, so the
// third SpMM runs over exactly those rows (~219K edges) instead of all 150K
// rows (4M edges): 18x less layer-3 work.
//  - setup: fp16 table init + single-pass ELL edge build (v7)
//  - layers 1,2: full SpMM (v8 loop), fp16 outputs h1, h2
//  - layer 3: sampled SpMM -> fp32 g_e3 rows (pure store)
//  - dot: acc = input + h1 + h2 + e3 on the fly; tail re-zeroes g_len

#define N_USERS 100000
#define M_ITEMS 50000
#define NN      (N_USERS + M_ITEMS)   // 150000
#define DVEC    16                    // D=64 floats = 16 float4
#define QVEC    8                     // D=64 halfs  = 8 uint4
#define ELEMN   (NN * DVEC)           // 2.4M float4
#define INV_SCALE (1.0f / 16.0f)      // 1/(LAYERS+1)^2
#define CAP     128                   // ELL row capacity (Poisson(26.7) safe)
#define CAPSH   7

// Static device scratch (allocation-free). Zero-initialized at module load.
__device__ uint4  g_h[3][NN * QVEC];      // fp16: h0=input, h1=e1, h2=e2
__device__ float4 g_e3[ELEMN];            // fp32 e3 (sampled rows only)
__device__ int    g_len[NN];              // ELL row lengths (zeroed by dot)
__device__ int2   g_edge[NN * CAP];       // padded ELL (col, val)

__device__ __forceinline__ unsigned pack_h2(float x, float y) {
    __half2 p = __floats2half2_rn(x, y);
    return *reinterpret_cast<unsigned*>(&p);
}

// ---------------------------------------------------------------------------
// setup: fp16 table init + single-pass ELL edge scatter (fused)
// ---------------------------------------------------------------------------
__global__ void lgcn_setup(const float* __restrict__ user_emb,
                           const float* __restrict__ item_emb,
                           const int*   __restrict__ rows,
                           const int*   __restrict__ cols,
                           const float* __restrict__ vals, int E) {
    int i = blockIdx.x * blockDim.x + threadIdx.x;
    if (i < ELEMN) {
        float4 v;
        if (i < N_USERS * DVEC) {
            v = reinterpret_cast<const float4*>(user_emb)[i];
        } else {
            v = reinterpret_cast<const float4*>(item_emb)[i - N_USERS * DVEC];
        }
        uint2* h2 = reinterpret_cast<uint2*>(g_h[0]);
        uint2 u;
        u.x = pack_h2(v.x, v.y);
        u.y = pack_h2(v.z, v.w);
        h2[i] = u;
    }
    for (int e = i; e < E; e += ELEMN) {
        int r   = __ldg(&rows[e]);
        int pos = atomicAdd(&g_len[r], 1);
        g_edge[(r << CAPSH) + pos] =
            make_int2(__ldg(&cols[e]), __float_as_int(__ldg(&vals[e])));
    }
}

// ---------------------------------------------------------------------------
// shared SpMM row body: one warp, 4 quarter-warp edge groups; each lane loads
// one uint4 (8 halves, 16B), 8 lanes cover the 128B fp16 row. fp32 accum.
// ---------------------------------------------------------------------------
__device__ __forceinline__ void fma8(float* a, float v, uint4 h) {
    float2 f0 = __half22float2(*reinterpret_cast<__half2*>(&h.x));
    float2 f1 = __half22float2(*reinterpret_cast<__half2*>(&h.y));
    float2 f2 = __half22float2(*reinterpret_cast<__half2*>(&h.z));
    float2 f3 = __half22float2(*reinterpret_cast<__half2*>(&h.w));
    a[0] += v * f0.x; a[1] += v * f0.y;
    a[2] += v * f1.x; a[3] += v * f1.y;
    a[4] += v * f2.x; a[5] += v * f2.y;
    a[6] += v * f3.x; a[7] += v * f3.y;
}

__device__ __forceinline__ void spmm_row_body(const uint4* __restrict__ S,
                                              int row, int grp, int comp,
                                              float* a) {
    int start = row << CAPSH;
    int end   = start + __ldg(&g_len[row]);

    #pragma unroll 2
    for (int e = start + grp; e < end; e += 4) {
        int2  cv = __ldg(&g_edge[e]);
        uint4 h  = __ldg(&S[(cv.x << 3) + comp]);
        fma8(a, __int_as_float(cv.y), h);
    }

    #pragma unroll
    for (int off = 8; off <= 16; off <<= 1) {
        #pragma unroll
        for (int k = 0; k < 8; k++)
            a[k] += __shfl_xor_sync(0xFFFFFFFFu, a[k], off);
    }
}

// ---------------------------------------------------------------------------
// full SpMM: one warp per node row, writes fp16 g_h[dst]
// ---------------------------------------------------------------------------
__global__ void lgcn_spmm_ell(int src, int dst) {
    int w = (blockIdx.x * blockDim.x + threadIdx.x) >> 5;   // row
    if (w >= NN) return;
    int lane = threadIdx.x & 31;
    int grp  = lane >> 3;
    int comp = lane & 7;

    float a[8] = {0.f, 0.f, 0.f, 0.f, 0.f, 0.f, 0.f, 0.f};
    spmm_row_body(g_h[src], w, grp, comp, a);

    if (grp == 0) {
        uint4 hout;
        hout.x = pack_h2(a[0], a[1]);
        hout.y = pack_h2(a[2], a[3]);
        hout.z = pack_h2(a[4], a[5]);
        hout.w = pack_h2(a[6], a[7]);
        g_h[dst][(w << 3) + comp] = hout;
    }
}

// ---------------------------------------------------------------------------
// sampled layer-3 SpMM: one warp per sample slot (2B slots), fp32 store.
// Duplicate rows store bit-identical values (same deterministic reduction).
// ---------------------------------------------------------------------------
__global__ void lgcn_spmm_e3(const int* __restrict__ users,
                             const int* __restrict__ items, int B) {
    int w = (blockIdx.x * blockDim.x + threadIdx.x) >> 5;   // sample slot
    if (w >= 2 * B) return;
    int lane = threadIdx.x & 31;
    int grp  = lane >> 3;
    int comp = lane & 7;

    int row = (w < B) ? __ldg(&users[w]) : (N_USERS + __ldg(&items[w - B]));

    float a[8] = {0.f, 0.f, 0.f, 0.f, 0.f, 0.f, 0.f, 0.f};
    spmm_row_body(g_h[2], row, grp, comp, a);

    if (grp == 0) {
        int o = row * DVEC + comp * 2;
        g_e3[o]     = make_float4(a[0], a[1], a[2], a[3]);
        g_e3[o + 1] = make_float4(a[4], a[5], a[6], a[7]);
    }
}

// ---------------------------------------------------------------------------
// dot: one warp per (user, item) pair.
// acc[node] = input_fp32[node] + h1[node] + h2[node] + e3[node], on the fly.
// Tail zeroes g_len for the next call.
// ---------------------------------------------------------------------------
__global__ void lgcn_dot(const int* __restrict__ users,
                         const int* __restrict__ items,
                         const float* __restrict__ uemb,
                         const float* __restrict__ iemb,
                         float* __restrict__ out, int B) {
    int gt   = blockIdx.x * blockDim.x + threadIdx.x;
    int w    = gt >> 5;
    int lane = gt & 31;

    if (w < B) {
        int u  = __ldg(&users[w]);
        int it = __ldg(&items[w]);
        int ni = N_USERS + it;

        const unsigned* H1 = reinterpret_cast<const unsigned*>(g_h[1]);
        const unsigned* H2 = reinterpret_cast<const unsigned*>(g_h[2]);
        const float2*   E3 = reinterpret_cast<const float2*>(g_e3);

        float2 su = __ldg(reinterpret_cast<const float2*>(uemb) + u * 32 + lane);
        {
            float2 t;
            t = __half22float2(*reinterpret_cast<const __half2*>(&H1[u * 32 + lane]));
            su.x += t.x; su.y += t.y;
            t = __half22float2(*reinterpret_cast<const __half2*>(&H2[u * 32 + lane]));
            su.x += t.x; su.y += t.y;
            float2 e = E3[u * 32 + lane];
            su.x += e.x; su.y += e.y;
        }
        float2 si = __ldg(reinterpret_cast<const float2*>(iemb) + it * 32 + lane);
        {
            float2 t;
            t = __half22float2(*reinterpret_cast<const __half2*>(&H1[ni * 32 + lane]));
            si.x += t.x; si.y += t.y;
            t = __half22float2(*reinterpret_cast<const __half2*>(&H2[ni * 32 + lane]));
            si.x += t.x; si.y += t.y;
            float2 e = E3[ni * 32 + lane];
            si.x += e.x; si.y += e.y;
        }

        float s = su.x * si.x + su.y * si.y;
        #pragma unroll
        for (int off = 16; off > 0; off >>= 1)
            s += __shfl_xor_sync(0xFFFFFFFFu, s, off);

        if (lane == 0) out[w] = s * INV_SCALE;
    }

    // precondition for next call: g_len = 0
    int nt = gridDim.x * blockDim.x;
    for (int i = gt; i < NN; i += nt) g_len[i] = 0;
}

// ---------------------------------------------------------------------------
// kernel_launch
// Inputs: 0 users(i32,B) 1 items(i32,B) 2 user_emb(f32) 3 item_emb(f32)
//         4 adj_rows(i32,NNZ) 5 adj_cols(i32,NNZ) 6 adj_vals(f32,NNZ)
// ---------------------------------------------------------------------------
extern "C" void kernel_launch(void* const* d_in, const int* in_sizes, int n_in,
                              void* d_out, int out_size) {
    const int*   users    = (const int*)  d_in[0];
    const int*   items    = (const int*)  d_in[1];
    const float* user_emb = (const float*)d_in[2];
    const float* item_emb = (const float*)d_in[3];
    const int*   rows     = (const int*)  d_in[4];
    const int*   cols     = (const int*)  d_in[5];
    const float* vals     = (const float*)d_in[6];
    float*       out      = (float*)      d_out;

    const int E = in_sizes[4];
    const int B = in_sizes[0];

    const int TPB    = 256;
    const int gSetup = (ELEMN + TPB - 1) / TPB;
    const int gSpmm  = (NN * 32 + TPB - 1) / TPB;
    const int gE3    = (2 * B * 32 + TPB - 1) / TPB;
    const int gDot   = (B * 32 + TPB - 1) / TPB;

    lgcn_setup<<<gSetup, TPB>>>(user_emb, item_emb, rows, cols, vals, E);

    lgcn_spmm_ell<<<gSpmm, TPB>>>(0, 1);              // e1 -> h1 (fp16, full)
    lgcn_spmm_ell<<<gSpmm, TPB>>>(1, 2);              // e2 -> h2 (fp16, full)
    lgcn_spmm_e3<<<gE3, TPB>>>(users, items, B);      // e3 at sampled rows only

    lgcn_dot<<<gDot, TPB>>>(users, items, user_emb, item_emb, out, B);
}